// round 7
// baseline (speedup 1.0000x reference)
#include <cuda_runtime.h>
#include <cstdint>
#include <math.h>

#define BSZ 8
#define SEQ 1024
#define DIM 1024
#define NH 16
#define DH 64
#define MTOK (BSZ*SEQ)        // 8192
#define FFD  (2*DIM)          // 2048

// ---------------- scratch (device globals; no runtime allocation) ----------
__device__ float g_q[MTOK*DIM];
__device__ float g_k[MTOK*DIM];
__device__ float g_v[MTOK*DIM];
__device__ float g_attn[MTOK*DIM];
__device__ float g_h1[MTOK*DIM];
__device__ float g_ffn[MTOK*FFD];
__device__ float g_xr[MTOK*DIM];          // tf32-rounded x
__device__ float g_wr[8*1024*1024];       // rounded weights: Wq,Wk,Wv,Wf,W1,W2

// ================= helpers =================================================
__device__ __forceinline__ uint32_t smem_u32(const void* p) {
    uint32_t a;
    asm("{ .reg .u64 t; cvta.to.shared.u64 t, %1; cvt.u32.u64 %0, t; }"
        : "=r"(a) : "l"(p));
    return a;
}
__device__ __forceinline__ float cvtf(float x) {
    uint32_t u; asm("cvt.rna.tf32.f32 %0, %1;" : "=r"(u) : "f"(x));
    return __uint_as_float(u);
}
#define CP_ASYNC16(s, g) \
    asm volatile("cp.async.cg.shared.global [%0], [%1], 16;" :: "r"(s), "l"(g))
#define CP_COMMIT() asm volatile("cp.async.commit_group;")
#define CP_WAIT1()  asm volatile("cp.async.wait_group 1;")
#define CP_WAIT3()  asm volatile("cp.async.wait_group 3;")

__device__ __forceinline__ void mma_tf32(float* d, const uint32_t* a, const uint32_t* b) {
    asm volatile(
        "mma.sync.aligned.m16n8k8.row.col.f32.tf32.tf32.f32 "
        "{%0,%1,%2,%3}, {%4,%5,%6,%7}, {%8,%9}, {%0,%1,%2,%3};"
        : "+f"(d[0]), "+f"(d[1]), "+f"(d[2]), "+f"(d[3])
        : "r"(a[0]), "r"(a[1]), "r"(a[2]), "r"(a[3]), "r"(b[0]), "r"(b[1]));
}

// ================= tf32 pre-round pass =====================================
__global__ __launch_bounds__(256) void round_copy(
    const float* __restrict__ in, float* __restrict__ out, int n4)
{
    int i = blockIdx.x * blockDim.x + threadIdx.x;
    int stride = gridDim.x * blockDim.x;
    for (; i < n4; i += stride) {
        float4 v = ((const float4*)in)[i];
        v.x = cvtf(v.x); v.y = cvtf(v.y); v.z = cvtf(v.z); v.w = cvtf(v.w);
        ((float4*)out)[i] = v;
    }
}

// ================= mma.sync tf32 GEMM (weight gemms, NT) ===================
__global__ __launch_bounds__(256, 2) void gemm_mma(
    const float* __restrict__ A, const float* __restrict__ B,
    const float* __restrict__ bias, const float* __restrict__ res,
    float* __restrict__ C, int K, int lda, int ldb, int ldc,
    float scale, int relu, int roundC)
{
    constexpr int NT = 128;
    constexpr int ASTR = 36, BSTR = 36;
    constexpr int AFL = 128 * ASTR, BFL = NT * BSTR;
    constexpr int WROWS = 2, WM = 64, WN = 32;
    constexpr int MT = 4, NTg = 4;

    extern __shared__ char dynsmem[];
    float* const AsB = (float*)dynsmem;
    float* const BsB = AsB + 2 * AFL;

    const int tid = threadIdx.x;
    const int wid = tid >> 5, lane = tid & 31;
    const int g = lane >> 2, t = lane & 3;
    const int wm = (wid % WROWS) * WM;
    const int wn = (wid / WROWS) * WN;

    const int n0 = blockIdx.x * NT;
    const int m0 = blockIdx.y * 128;

    float acc[MT][NTg][4];
#pragma unroll
    for (int i = 0; i < MT; i++)
#pragma unroll
        for (int j = 0; j < NTg; j++)
#pragma unroll
            for (int q = 0; q < 4; q++) acc[i][j][q] = 0.f;

    const int Kc = K >> 5;

    auto load_slab = [&](int c, int buf) {
        const int kt = c << 5;
        float* As = AsB + buf * AFL;
        float* Bs = BsB + buf * BFL;
#pragma unroll
        for (int i = 0; i < 4; i++) {
            const int lin = i * 256 + tid;
            const int row = lin >> 3, c16 = lin & 7;
            CP_ASYNC16(smem_u32(As + row * ASTR + c16 * 4),
                       A + (size_t)(m0 + row) * lda + kt + c16 * 4);
        }
#pragma unroll
        for (int i = 0; i < 4; i++) {
            const int lin = i * 256 + tid;
            const int row = lin >> 3, c16 = lin & 7;
            CP_ASYNC16(smem_u32(Bs + row * BSTR + c16 * 4),
                       B + (size_t)(n0 + row) * ldb + kt + c16 * 4);
        }
    };

    load_slab(0, 0);
    CP_COMMIT();

    for (int c = 0; c < Kc; c++) {
        if (c + 1 < Kc) load_slab(c + 1, (c + 1) & 1);
        CP_COMMIT();
        CP_WAIT1();
        __syncthreads();

        const float* As = AsB + (c & 1) * AFL;
        const float* Bs = BsB + (c & 1) * BFL;
#pragma unroll
        for (int ks = 0; ks < 4; ks++) {
            const int kk = ks * 8;
            uint32_t af[MT][4];
#pragma unroll
            for (int mt = 0; mt < MT; mt++) {
                const float* ar = As + (wm + mt * 16 + g) * ASTR + kk + t;
                af[mt][0] = __float_as_uint(ar[0]);
                af[mt][1] = __float_as_uint(ar[8 * ASTR]);
                af[mt][2] = __float_as_uint(ar[4]);
                af[mt][3] = __float_as_uint(ar[8 * ASTR + 4]);
            }
            uint32_t bf[NTg][2];
#pragma unroll
            for (int nt = 0; nt < NTg; nt++) {
                const float* br = Bs + (wn + nt * 8 + g) * BSTR + kk + t;
                bf[nt][0] = __float_as_uint(br[0]);
                bf[nt][1] = __float_as_uint(br[4]);
            }
#pragma unroll
            for (int mt = 0; mt < MT; mt++)
#pragma unroll
                for (int nt = 0; nt < NTg; nt++)
                    mma_tf32(acc[mt][nt], af[mt], bf[nt]);
        }
        __syncthreads();
    }

#pragma unroll
    for (int mt = 0; mt < MT; mt++) {
        const int row = m0 + wm + mt * 16 + g;
#pragma unroll
        for (int nt = 0; nt < NTg; nt++) {
            const int col = n0 + wn + nt * 8 + 2 * t;
            float o0 = acc[mt][nt][0], o1 = acc[mt][nt][1];
            float o2 = acc[mt][nt][2], o3 = acc[mt][nt][3];
            if (bias) {
                const float b0 = bias[col], b1 = bias[col + 1];
                o0 += b0; o1 += b1; o2 += b0; o3 += b1;
            }
            if (scale != 1.f) { o0 *= scale; o1 *= scale; o2 *= scale; o3 *= scale; }
            if (res) {
                float2 r0 = *(const float2*)&res[(size_t)row * ldc + col];
                float2 r1 = *(const float2*)&res[(size_t)(row + 8) * ldc + col];
                o0 += r0.x; o1 += r0.y; o2 += r1.x; o3 += r1.y;
            }
            if (relu) {
                o0 = fmaxf(o0, 0.f); o1 = fmaxf(o1, 0.f);
                o2 = fmaxf(o2, 0.f); o3 = fmaxf(o3, 0.f);
            }
            if (roundC) {
                o0 = cvtf(o0); o1 = cvtf(o1); o2 = cvtf(o2); o3 = cvtf(o3);
            }
            *(float2*)&C[(size_t)row * ldc + col]       = make_float2(o0, o1);
            *(float2*)&C[(size_t)(row + 8) * ldc + col] = make_float2(o2, o3);
        }
    }
}

// ================= fused attention: scores + softmax + PV ==================
// CTA: 32 q-rows of one (b,h). S row-block (32x1024) resident in smem.
// Phase 1: S = Q @ K^T (Q frags register-resident; K via 4-deep cp.async ring)
// Phase 2: softmax rows in smem (mask col 1023), write fp32 P to gmem once
// Phase 3: attn = P @ V (V via same ring), epilogue tf32-round
#define QR 32
#define KCH 64
#define SSTR 1028u
#define QSTR 68u
#define KVSTR 76u
#define NCH (SEQ/KCH)   // 16

__global__ __launch_bounds__(256, 1) void attn_fused(
    const float* __restrict__ q, const float* __restrict__ k,
    const float* __restrict__ v, float* __restrict__ score,
    float* __restrict__ attn)
{
    extern __shared__ char dynsmem[];
    float* const S  = (float*)dynsmem;                  // 32 x 1028
    float* const Qs = S + QR * SSTR;                    // 32 x 68
    float* const KV = Qs + QR * QSTR;                   // 4 x (64 x 76)

    const int tid = threadIdx.x;
    const int wid = tid >> 5, lane = tid & 31;
    const int g = lane >> 2, t = lane & 3;
    const int i0 = blockIdx.x * QR;
    const int bh = blockIdx.y;
    const int b = bh >> 4, h = bh & 15;

    const float* Qg = q + ((size_t)(b * SEQ + i0)) * DIM + h * DH;
    const float* Kg = k + ((size_t)b * SEQ) * DIM + h * DH;
    const float* Vg = v + ((size_t)b * SEQ) * DIM + h * DH;

    auto load_kv = [&](const float* base, int chunk) {
        float* dst = KV + (chunk & 3) * (KCH * KVSTR);
#pragma unroll
        for (int i = 0; i < 4; i++) {
            const int lin = i * 256 + tid;
            const int row = lin >> 4, c16 = lin & 15;
            CP_ASYNC16(smem_u32(dst + row * KVSTR + c16 * 4),
                       base + (size_t)(chunk * KCH + row) * DIM + c16 * 4);
        }
    };

    // ---- prologue: Q tile + first 3 K chunks ----
#pragma unroll
    for (int i = 0; i < 2; i++) {
        const int lin = i * 256 + tid;
        const int row = lin >> 4, c16 = lin & 15;
        CP_ASYNC16(smem_u32(Qs + row * QSTR + c16 * 4),
                   Qg + (size_t)row * DIM + c16 * 4);
    }
    CP_COMMIT();
    load_kv(Kg, 0); CP_COMMIT();
    load_kv(Kg, 1); CP_COMMIT();
    load_kv(Kg, 2); CP_COMMIT();

    CP_WAIT3();          // Q ready
    __syncthreads();

    // ---- phase 1: QK^T ----
    {
        // preload Q fragments: rows 0..31 (MT=2), K=64 (8 k-steps)
        uint32_t af[2][8][4];
#pragma unroll
        for (int mt = 0; mt < 2; mt++)
#pragma unroll
            for (int ks = 0; ks < 8; ks++) {
                const float* ar = Qs + (mt * 16 + g) * QSTR + ks * 8 + t;
                af[mt][ks][0] = __float_as_uint(ar[0]);
                af[mt][ks][1] = __float_as_uint(ar[8 * QSTR]);
                af[mt][ks][2] = __float_as_uint(ar[4]);
                af[mt][ks][3] = __float_as_uint(ar[8 * QSTR + 4]);
            }

        for (int c = 0; c < NCH; c++) {
            if (c + 3 < NCH) load_kv(Kg, c + 3);
            CP_COMMIT();
            CP_WAIT3();
            __syncthreads();

            const float* Ks = KV + (c & 3) * (KCH * KVSTR);
            // warp w -> keys [w*8, w*8+8) within chunk
            float acc[2][4];
#pragma unroll
            for (int mt = 0; mt < 2; mt++)
#pragma unroll
                for (int qq = 0; qq < 4; qq++) acc[mt][qq] = 0.f;
#pragma unroll
            for (int ks = 0; ks < 8; ks++) {
                const int kk = ks * 8;
                uint32_t bf[2];
                const float* br = Ks + (wid * 8 + g) * KVSTR + kk + t;
                bf[0] = __float_as_uint(br[0]);
                bf[1] = __float_as_uint(br[4]);
                mma_tf32(acc[0], af[0][ks], bf);
                mma_tf32(acc[1], af[1][ks], bf);
            }
            // write S tile: rows mt*16+g(+8), cols c*64 + wid*8 + 2t(+1)
            const int colb = c * KCH + wid * 8 + 2 * t;
#pragma unroll
            for (int mt = 0; mt < 2; mt++) {
                *(float2*)&S[(mt * 16 + g) * SSTR + colb] =
                    make_float2(acc[mt][0], acc[mt][1]);
                *(float2*)&S[(mt * 16 + g + 8) * SSTR + colb] =
                    make_float2(acc[mt][2], acc[mt][3]);
            }
            __syncthreads();
        }
    }

    // ---- prefetch V chunks 0..2 (overlaps softmax) ----
    load_kv(Vg, 0); CP_COMMIT();
    load_kv(Vg, 1); CP_COMMIT();
    load_kv(Vg, 2); CP_COMMIT();

    // ---- phase 2: softmax rows (warp = 4 rows), write P to gmem ----
    {
#pragma unroll
        for (int rr = 0; rr < 4; rr++) {
            const int r = wid * 4 + rr;
            float* srow = S + r * SSTR;
            float vals[32];
            float m = -INFINITY;
#pragma unroll
            for (int i = 0; i < 32; i++) {
                float x = srow[lane + 32 * i];
                if (lane + 32 * i == SEQ - 1) x = -INFINITY;
                vals[i] = x;
                m = fmaxf(m, x);
            }
#pragma unroll
            for (int o = 16; o; o >>= 1)
                m = fmaxf(m, __shfl_xor_sync(0xffffffffu, m, o));
            float s = 0.f;
#pragma unroll
            for (int i = 0; i < 32; i++) {
                vals[i] = (lane + 32 * i == SEQ - 1) ? 0.f : __expf(vals[i] - m);
                s += vals[i];
            }
#pragma unroll
            for (int o = 16; o; o >>= 1)
                s += __shfl_xor_sync(0xffffffffu, s, o);
            const float inv = 1.f / s;
            float* prow = score + ((size_t)bh * SEQ + i0 + r) * SEQ;
#pragma unroll
            for (int i = 0; i < 32; i++) {
                const float pv = vals[i] * inv;
                srow[lane + 32 * i] = pv;
                prow[lane + 32 * i] = pv;
            }
        }
    }
    __syncthreads();

    // ---- phase 3: attn = P @ V ----
    {
        // warp tile 16x16: wm=(wid&1)*16, wn=(wid>>1)*16; MT=1, NTg=2
        const int wm = (wid & 1) * 16;
        const int wn = (wid >> 1) * 16;
        float acc[2][4];
#pragma unroll
        for (int nt = 0; nt < 2; nt++)
#pragma unroll
            for (int qq = 0; qq < 4; qq++) acc[nt][qq] = 0.f;

        for (int c = 0; c < NCH; c++) {
            if (c + 3 < NCH) load_kv(Vg, c + 3);
            CP_COMMIT();
            CP_WAIT3();
            __syncthreads();

            const float* Vs = KV + (c & 3) * (KCH * KVSTR);
            const int kc = c * KCH;
#pragma unroll
            for (int ks = 0; ks < 8; ks++) {
                const int kk = ks * 8;
                uint32_t af[4];
                const float* ar = S + (wm + g) * SSTR + kc + kk + t;
                af[0] = __float_as_uint(ar[0]);
                af[1] = __float_as_uint(ar[8 * SSTR]);
                af[2] = __float_as_uint(ar[4]);
                af[3] = __float_as_uint(ar[8 * SSTR + 4]);
                uint32_t bf[2][2];
#pragma unroll
                for (int nt = 0; nt < 2; nt++) {
                    const float* br = Vs + (kk + t) * KVSTR + wn + nt * 8 + g;
                    bf[nt][0] = __float_as_uint(br[0]);
                    bf[nt][1] = __float_as_uint(br[4 * KVSTR]);
                }
                mma_tf32(acc[0], af, bf[0]);
                mma_tf32(acc[1], af, bf[1]);
            }
            __syncthreads();
        }

        // epilogue: tf32-round (feeds Wf gemm)
#pragma unroll
        for (int nt = 0; nt < 2; nt++) {
            const int col = h * DH + wn + nt * 8 + 2 * t;
            const size_t r0 = (size_t)(b * SEQ + i0 + wm + g) * DIM + col;
            const size_t r1 = (size_t)(b * SEQ + i0 + wm + g + 8) * DIM + col;
            attn[r0]     = cvtf(acc[nt][0]);
            attn[r0 + 1] = cvtf(acc[nt][1]);
            attn[r1]     = cvtf(acc[nt][2]);
            attn[r1 + 1] = cvtf(acc[nt][3]);
        }
    }
}

// ================= layernorm ==============================================
__global__ __launch_bounds__(256) void layernorm_row(
    const float* __restrict__ in, float* __restrict__ out,
    const float* __restrict__ g, const float* __restrict__ be, int roundC)
{
    __shared__ float sm[8], sq[8];
    const size_t base = (size_t)blockIdx.x * DIM;
    const int tid = threadIdx.x;
    const int lane = tid & 31, wid = tid >> 5;

    float4 v = *(const float4*)&in[base + tid*4];
    float s  = v.x + v.y + v.z + v.w;
    float s2 = v.x*v.x + v.y*v.y + v.z*v.z + v.w*v.w;
#pragma unroll
    for (int o = 16; o; o >>= 1) {
        s  += __shfl_xor_sync(0xffffffffu, s,  o);
        s2 += __shfl_xor_sync(0xffffffffu, s2, o);
    }
    if (lane == 0) { sm[wid] = s; sq[wid] = s2; }
    __syncthreads();
    if (tid == 0) {
        float tt = 0.f, t2 = 0.f;
#pragma unroll
        for (int i = 0; i < 8; i++) { tt += sm[i]; t2 += sq[i]; }
        sm[0] = tt; sq[0] = t2;
    }
    __syncthreads();
    const float mean = sm[0] * (1.f / DIM);
    const float var  = sq[0] * (1.f / DIM) - mean * mean;
    const float r = rsqrtf(var + 1e-5f);

    float4 gg = *(const float4*)&g[tid*4];
    float4 bb = *(const float4*)&be[tid*4];
    float4 o4;
    o4.x = (v.x - mean) * r * gg.x + bb.x;
    o4.y = (v.y - mean) * r * gg.y + bb.y;
    o4.z = (v.z - mean) * r * gg.z + bb.z;
    o4.w = (v.w - mean) * r * gg.w + bb.w;
    if (roundC) {
        o4.x = cvtf(o4.x); o4.y = cvtf(o4.y);
        o4.z = cvtf(o4.z); o4.w = cvtf(o4.w);
    }
    *(float4*)&out[base + tid*4] = o4;
}

// ================= launcher ================================================
static const int SMEM_GEMM = 2 * (128*36 + 128*36) * 4;                 // 73728
static const int SMEM_ATT  = (QR*SSTR + QR*QSTR + 4*KCH*KVSTR) * 4;     // 218112

extern "C" void kernel_launch(void* const* d_in, const int* in_sizes, int n_in,
                              void* d_out, int out_size)
{
    const float* x  = (const float*)d_in[0];
    const float* Wq = (const float*)d_in[1];
    const float* bq = (const float*)d_in[2];
    const float* Wk = (const float*)d_in[3];
    const float* bk = (const float*)d_in[4];
    const float* Wv = (const float*)d_in[5];
    const float* bv = (const float*)d_in[6];
    const float* Wf = (const float*)d_in[7];
    const float* bf = (const float*)d_in[8];
    const float* W1 = (const float*)d_in[9];
    const float* b1 = (const float*)d_in[10];
    const float* W2 = (const float*)d_in[11];
    const float* b2 = (const float*)d_in[12];
    const float* g1 = (const float*)d_in[13];
    const float* be1= (const float*)d_in[14];
    const float* g2 = (const float*)d_in[15];
    const float* be2= (const float*)d_in[16];

    float* out   = (float*)d_out;
    float* score = out + (size_t)MTOK * DIM;

    float *pq, *pk, *pv, *pattn, *ph1, *pffn, *pxr, *pwr;
    cudaGetSymbolAddress((void**)&pq,    g_q);
    cudaGetSymbolAddress((void**)&pk,    g_k);
    cudaGetSymbolAddress((void**)&pv,    g_v);
    cudaGetSymbolAddress((void**)&pattn, g_attn);
    cudaGetSymbolAddress((void**)&ph1,   g_h1);
    cudaGetSymbolAddress((void**)&pffn,  g_ffn);
    cudaGetSymbolAddress((void**)&pxr,   g_xr);
    cudaGetSymbolAddress((void**)&pwr,   g_wr);

    float* rWq = pwr;
    float* rWk = pwr + 1*1024*1024;
    float* rWv = pwr + 2*1024*1024;
    float* rWf = pwr + 3*1024*1024;
    float* rW1 = pwr + 4*1024*1024;
    float* rW2 = pwr + 6*1024*1024;

    cudaFuncSetAttribute(gemm_mma, cudaFuncAttributeMaxDynamicSharedMemorySize, SMEM_GEMM);
    cudaFuncSetAttribute(attn_fused, cudaFuncAttributeMaxDynamicSharedMemorySize, SMEM_ATT);

    const float isq = 0.125f;  // 1/sqrt(64)

    // ---- pre-round GEMM operands to tf32 ----
    round_copy<<<2048, 256>>>(x,  pxr, MTOK*DIM/4);
    round_copy<<<1024, 256>>>(Wq, rWq, DIM*DIM/4);
    round_copy<<<1024, 256>>>(Wk, rWk, DIM*DIM/4);
    round_copy<<<1024, 256>>>(Wv, rWv, DIM*DIM/4);
    round_copy<<<1024, 256>>>(Wf, rWf, DIM*DIM/4);
    round_copy<<<2048, 256>>>(W1, rW1, FFD*DIM/4);
    round_copy<<<2048, 256>>>(W2, rW2, FFD*DIM/4);

    // QKV projections (outputs tf32-rounded: feed attention mma)
    gemm_mma<<<dim3(DIM/128, MTOK/128), 256, SMEM_GEMM>>>(
        pxr, rWq, bq, nullptr, pq, DIM, DIM, DIM, DIM, isq, 0, 1);
    gemm_mma<<<dim3(DIM/128, MTOK/128), 256, SMEM_GEMM>>>(
        pxr, rWk, bk, nullptr, pk, DIM, DIM, DIM, DIM, 1.f, 0, 1);
    gemm_mma<<<dim3(DIM/128, MTOK/128), 256, SMEM_GEMM>>>(
        pxr, rWv, bv, nullptr, pv, DIM, DIM, DIM, DIM, 1.f, 0, 1);

    // fused scores + softmax + PV (P -> score region of d_out, fp32)
    attn_fused<<<dim3(SEQ/QR, BSZ*NH), 256, SMEM_ATT>>>(
        pq, pk, pv, score, pattn);

    // output projection + residual (exact x), LN1 (rounded: feeds W1)
    gemm_mma<<<dim3(DIM/128, MTOK/128), 256, SMEM_GEMM>>>(
        pattn, rWf, bf, x, ph1, DIM, DIM, DIM, DIM, 1.f, 0, 0);
    layernorm_row<<<MTOK, 256>>>(ph1, ph1, g1, be1, 1);

    // FFN: W1 out rounded (feeds W2); W2 out exact
    gemm_mma<<<dim3(FFD/128, MTOK/128), 256, SMEM_GEMM>>>(
        ph1, rW1, b1, nullptr, pffn, DIM, DIM, DIM, FFD, 1.f, 1, 1);
    gemm_mma<<<dim3(DIM/128, MTOK/128), 256, SMEM_GEMM>>>(
        pffn, rW2, b2, ph1, pq, FFD, FFD, FFD, DIM, 1.f, 0, 0);
    layernorm_row<<<MTOK, 256>>>(pq, out, g2, be2, 0);
}